// round 7
// baseline (speedup 1.0000x reference)
#include <cuda_runtime.h>
#include <cuda_bf16.h>
#include <math.h>

// Problem dims (fixed by the dataset)
#define BATCH   2
#define SEQ     2048
#define HID     1024
#define NHEAD   16
#define DH      64          // head dim
#define ROWS    (BATCH*SEQ) // 4096

// ---------------- scratch (no allocs allowed) ----------------
__device__ float g_qp[ROWS * HID];
__device__ float g_kp[ROWS * HID];
__device__ float g_vp[ROWS * HID];
__device__ float g_ctx[ROWS * HID];

// ---------------- f32x2 packed helpers (sm_103a) ----------------
typedef unsigned long long u64f2;

__device__ __forceinline__ void fma2(u64f2 &d, u64f2 a, u64f2 b) {
    asm("fma.rn.f32x2 %0, %1, %2, %0;" : "+l"(d) : "l"(a), "l"(b));
}
__device__ __forceinline__ u64f2 pack2(float lo, float hi) {
    u64f2 r; asm("mov.b64 %0, {%1, %2};" : "=l"(r) : "f"(lo), "f"(hi)); return r;
}
__device__ __forceinline__ float2 unpack2(u64f2 v) {
    float2 r; asm("mov.b64 {%0, %1}, %2;" : "=f"(r.x), "=f"(r.y) : "l"(v)); return r;
}
__device__ __forceinline__ void mul2(u64f2 &d, u64f2 a) {
    asm("mul.rn.f32x2 %0, %0, %1;" : "+l"(d) : "l"(a));
}

// ---------------- GEMM: C[M,N] = A[M,K] @ B[K,N] + bias[N] ----------------
// 128x128 tile, BK=16, 256 threads, 8x8 microtile.
// K-paired f32x2: As[m][k] (stride 20), Bs[n][k] transposed (stride 18).
// Inner loop is pure LDS.64 + fma2 — no packing.
#define GBM 128
#define GBN 128
#define GBK 16
#define ASTR 20
#define BSTR 18

__global__ __launch_bounds__(256) void sgemm_bias_kernel(
    const float* __restrict__ A, const float* __restrict__ B,
    const float* __restrict__ bias, float* __restrict__ C,
    int M, int N, int K)
{
    __shared__ float As[2][GBM * ASTR];
    __shared__ float Bs[2][GBN * BSTR];

    const int tid = threadIdx.x;
    const int tr  = tid >> 4;        // 0..15 -> rows tr*8..tr*8+7
    const int tc  = tid & 15;        // 0..15 -> cols j*16+tc
    const int row0 = blockIdx.y * GBM;
    const int col0 = blockIdx.x * GBN;

    // A fill: arow 0..127, acol in {0,8}; two float4 per thread
    const int arow = tid >> 1;
    const int acol = (tid & 1) * 8;
    const float* Aptr = A + (size_t)(row0 + arow) * K + acol;

    // B fill (transpose): n = tid&127 (col), kg = tid>>7 in {0,1}; 8 scalar LDGs down column
    const int bn = tid & 127;
    const int bkg = (tid >> 7) * 8;
    const float* Bptr = B + (size_t)bkg * N + col0 + bn;

    u64f2 acc2[8][8];
#pragma unroll
    for (int i = 0; i < 8; i++)
#pragma unroll
        for (int j = 0; j < 8; j++) acc2[i][j] = 0ull;

    // ---- prologue: fill tile 0 ----
    {
        float4 a0 = *reinterpret_cast<const float4*>(Aptr);
        float4 a1 = *reinterpret_cast<const float4*>(Aptr + 4);
        *reinterpret_cast<float4*>(&As[0][arow * ASTR + acol])     = a0;
        *reinterpret_cast<float4*>(&As[0][arow * ASTR + acol + 4]) = a1;
        float bt[8];
#pragma unroll
        for (int t = 0; t < 8; t++) bt[t] = Bptr[(size_t)t * N];
#pragma unroll
        for (int p = 0; p < 4; p++)
            *reinterpret_cast<float2*>(&Bs[0][bn * BSTR + bkg + 2 * p]) =
                make_float2(bt[2 * p], bt[2 * p + 1]);
    }
    __syncthreads();

    int cur = 0;
    for (int k0 = 0; k0 < K; k0 += GBK) {
        const int kn = k0 + GBK;
        const bool has_next = (kn < K);
        float4 a0n, a1n; float btn[8];
        if (has_next) {
            a0n = *reinterpret_cast<const float4*>(Aptr + kn);
            a1n = *reinterpret_cast<const float4*>(Aptr + kn + 4);
#pragma unroll
            for (int t = 0; t < 8; t++) btn[t] = Bptr[(size_t)(kn + t) * N];
        }

#pragma unroll
        for (int kk = 0; kk < GBK; kk += 2) {
            u64f2 a2[8], b2[8];
#pragma unroll
            for (int i = 0; i < 8; i++)
                a2[i] = *reinterpret_cast<const u64f2*>(&As[cur][(tr * 8 + i) * ASTR + kk]);
#pragma unroll
            for (int j = 0; j < 8; j++)
                b2[j] = *reinterpret_cast<const u64f2*>(&Bs[cur][(j * 16 + tc) * BSTR + kk]);
#pragma unroll
            for (int i = 0; i < 8; i++)
#pragma unroll
                for (int j = 0; j < 8; j++)
                    fma2(acc2[i][j], a2[i], b2[j]);
        }

        if (has_next) {
            const int nxt = cur ^ 1;
            *reinterpret_cast<float4*>(&As[nxt][arow * ASTR + acol])     = a0n;
            *reinterpret_cast<float4*>(&As[nxt][arow * ASTR + acol + 4]) = a1n;
#pragma unroll
            for (int p = 0; p < 4; p++)
                *reinterpret_cast<float2*>(&Bs[nxt][bn * BSTR + bkg + 2 * p]) =
                    make_float2(btn[2 * p], btn[2 * p + 1]);
            __syncthreads();
            cur = nxt;
        }
    }

    float bb[8];
#pragma unroll
    for (int j = 0; j < 8; j++) bb[j] = bias[col0 + j * 16 + tc];

#pragma unroll
    for (int i = 0; i < 8; i++) {
        const int row = row0 + tr * 8 + i;
        float* cp = C + (size_t)row * N + col0 + tc;
#pragma unroll
        for (int j = 0; j < 8; j++) {
            float2 v = unpack2(acc2[i][j]);
            cp[j * 16] = v.x + v.y + bb[j];
        }
    }
}

// ---------------- flash attention (fp32 + f32x2, pack-free) ----------------
// Block: 64 q-rows, 64-k tiles, 128 threads (8x16), microtile 8(q) x 4(k/d).
// Qs/Ps plain [row][64]; Ks row-major XOR-swizzled; Vs TRANSPOSED [d][k] XOR-swizzled.
#define ATQ 64
#define ATK 64

__global__ __launch_bounds__(128) void attn_kernel(
    const float* __restrict__ qp, const float* __restrict__ kp,
    const float* __restrict__ vp, const int* __restrict__ mask,
    float* __restrict__ ctx)
{
    extern __shared__ float sm[];
    float* Qs = sm;               // [64][64] plain
    float* Ks = sm + 4096;        // [64][64] swizzled (row=k, col=d)
    float* Vs = sm + 8192;        // [64][64] TRANSPOSED swizzled (row=d, col=k)
    float* Ps = sm + 12288;       // [64][64] plain (row=q, col=k)

    const int tid = threadIdx.x;
    const int qt = blockIdx.x, h = blockIdx.y, b = blockIdx.z;
    const int q0 = qt * ATQ;
    const int tr = tid >> 4;   // 0..7  -> q-rows tr*8 .. tr*8+7
    const int tc = tid & 15;   // 0..15 -> k/d cols tc*4 .. tc*4+3

    const float* qbase = qp + ((size_t)(b * SEQ + q0) * HID) + h * DH;
    const float* kbase = kp + ((size_t)b * SEQ) * HID + h * DH;
    const float* vbase = vp + ((size_t)b * SEQ) * HID + h * DH;
    const int*   mbase = mask + (size_t)(b * SEQ + q0) * SEQ;

    // load Q tile once (plain layout)
#pragma unroll
    for (int t = 0; t < 8; t++) {
        const int f = t * 128 + tid;
        const int r = f >> 4, c4 = f & 15;
        *reinterpret_cast<float4*>(&Qs[r * 64 + c4 * 4]) =
            *reinterpret_cast<const float4*>(&qbase[(size_t)r * HID + c4 * 4]);
    }

    float m[8], l[8];
    u64f2 acc2[8][4];
#pragma unroll
    for (int i = 0; i < 8; i++) {
        m[i] = -1e30f; l[i] = 0.f;
#pragma unroll
        for (int j = 0; j < 4; j++) acc2[i][j] = 0ull;
    }

    const float scale = 0.125f; // 1/sqrt(64)

    for (int kt = 0; kt < SEQ; kt += ATK) {
        __syncthreads();  // previous readers done with Ks/Vs/Ps
        // load K (row-swizzled) + V (transposed, swizzled)
#pragma unroll
        for (int t = 0; t < 8; t++) {
            const int f = t * 128 + tid;
            const int r = f >> 4, c4 = f & 15;
            float4 kv = *reinterpret_cast<const float4*>(&kbase[(size_t)(kt + r) * HID + c4 * 4]);
            float4 vv = *reinterpret_cast<const float4*>(&vbase[(size_t)(kt + r) * HID + c4 * 4]);
            const int kslot = c4 ^ (r >> 2);
            *reinterpret_cast<float4*>(&Ks[r * 64 + kslot * 4]) = kv;
            // V transpose: element (d = c4*4+u, k = r) -> Vs[d*64 + ((r>>2)^c4)*4 + (r&3)]
            const int voff = (((r >> 2) ^ c4) << 2) | (r & 3);
            Vs[(c4 * 4 + 0) * 64 + voff] = vv.x;
            Vs[(c4 * 4 + 1) * 64 + voff] = vv.y;
            Vs[(c4 * 4 + 2) * 64 + voff] = vv.z;
            Vs[(c4 * 4 + 3) * 64 + voff] = vv.w;
        }
        __syncthreads();

        // ---- scores: s2[i][j] over kk-pairs (Q plain, K swizzled) ----
        u64f2 s2[8][4];
#pragma unroll
        for (int i = 0; i < 8; i++)
#pragma unroll
            for (int j = 0; j < 4; j++) s2[i][j] = 0ull;

        {
            const float* qrow = Qs + (tr * 8) * 64;
            const float* krow = Ks + (tc * 4) * 64;
#pragma unroll 4
            for (int kk = 0; kk < ATK; kk += 2) {
                const int so = (((kk >> 2) ^ tc) << 2) | (kk & 3);
                u64f2 b2[4];
#pragma unroll
                for (int j = 0; j < 4; j++)
                    b2[j] = *reinterpret_cast<const u64f2*>(krow + j * 64 + so);
#pragma unroll
                for (int i = 0; i < 8; i++) {
                    const u64f2 a2 = *reinterpret_cast<const u64f2*>(qrow + i * 64 + kk);
#pragma unroll
                    for (int j = 0; j < 4; j++)
                        fma2(s2[i][j], a2, b2[j]);
                }
            }
        }

        // ---- scale + mask + online softmax, write P ----
#pragma unroll
        for (int i = 0; i < 8; i++) {
            float s[4];
#pragma unroll
            for (int j = 0; j < 4; j++) {
                float2 v = unpack2(s2[i][j]);
                s[j] = v.x + v.y;
            }
            const int4 mk = *reinterpret_cast<const int4*>(
                mbase + (size_t)(tr * 8 + i) * SEQ + kt + tc * 4);
            s[0] = mk.x ? s[0] * scale : -10000.f;
            s[1] = mk.y ? s[1] * scale : -10000.f;
            s[2] = mk.z ? s[2] * scale : -10000.f;
            s[3] = mk.w ? s[3] * scale : -10000.f;

            float mt = fmaxf(fmaxf(s[0], s[1]), fmaxf(s[2], s[3]));
#pragma unroll
            for (int off = 8; off; off >>= 1)
                mt = fmaxf(mt, __shfl_xor_sync(0xffffffffu, mt, off));
            const float mn = fmaxf(m[i], mt);
            const float alpha = __expf(m[i] - mn);
            m[i] = mn;

            float lt = 0.f;
#pragma unroll
            for (int j = 0; j < 4; j++) {
                s[j] = __expf(s[j] - mn);
                lt += s[j];
            }
#pragma unroll
            for (int off = 8; off; off >>= 1)
                lt += __shfl_xor_sync(0xffffffffu, lt, off);
            l[i] = l[i] * alpha + lt;

            const u64f2 al2 = pack2(alpha, alpha);
#pragma unroll
            for (int j = 0; j < 4; j++) mul2(acc2[i][j], al2);

            *reinterpret_cast<float4*>(&Ps[(tr * 8 + i) * 64 + tc * 4]) =
                make_float4(s[0], s[1], s[2], s[3]);
        }
        __syncthreads();

        // ---- O += P @ V (P plain k-contig, V transposed swizzled) — pack-free ----
        {
            const float* prow = Ps + (tr * 8) * 64;
            const float* vrow = Vs + (tc * 4) * 64;
#pragma unroll 4
            for (int kk = 0; kk < ATK; kk += 2) {
                const int so = (((kk >> 2) ^ tc) << 2) | (kk & 3);
                u64f2 v2[4];
#pragma unroll
                for (int j = 0; j < 4; j++)
                    v2[j] = *reinterpret_cast<const u64f2*>(vrow + j * 64 + so);
#pragma unroll
                for (int i = 0; i < 8; i++) {
                    const u64f2 a2 = *reinterpret_cast<const u64f2*>(prow + i * 64 + kk);
#pragma unroll
                    for (int j = 0; j < 4; j++)
                        fma2(acc2[i][j], a2, v2[j]);
                }
            }
        }
    }

    // write: ctx[b, q, h*64 + d]
#pragma unroll
    for (int i = 0; i < 8; i++) {
        const float inv = 1.f / l[i];
        const int q = q0 + tr * 8 + i;
        float* o = ctx + ((size_t)(b * SEQ + q) * HID) + h * DH + tc * 4;
        float r[4];
#pragma unroll
        for (int j = 0; j < 4; j++) {
            float2 v = unpack2(acc2[i][j]);
            r[j] = (v.x + v.y) * inv;
        }
        *reinterpret_cast<float4*>(o) = make_float4(r[0], r[1], r[2], r[3]);
    }
}

// ---------------- launch ----------------
extern "C" void kernel_launch(void* const* d_in, const int* in_sizes, int n_in,
                              void* d_out, int out_size)
{
    const float* q    = (const float*)d_in[0];
    const float* k    = (const float*)d_in[1];
    const float* v    = (const float*)d_in[2];
    const int*   mask = (const int*)  d_in[3];
    const float* w_q  = (const float*)d_in[4];
    const float* b_q  = (const float*)d_in[5];
    const float* w_k  = (const float*)d_in[6];
    const float* b_k  = (const float*)d_in[7];
    const float* w_v  = (const float*)d_in[8];
    const float* b_v  = (const float*)d_in[9];
    const float* w_o  = (const float*)d_in[10];
    const float* b_o  = (const float*)d_in[11];
    float* out = (float*)d_out;

    float *qp, *kp, *vp, *ctx;
    cudaGetSymbolAddress((void**)&qp,  g_qp);
    cudaGetSymbolAddress((void**)&kp,  g_kp);
    cudaGetSymbolAddress((void**)&vp,  g_vp);
    cudaGetSymbolAddress((void**)&ctx, g_ctx);

    const dim3 gemm_grid(HID / GBN, ROWS / GBM);  // (8, 32)
    sgemm_bias_kernel<<<gemm_grid, 256>>>(q, w_q, b_q, qp, ROWS, HID, HID);
    sgemm_bias_kernel<<<gemm_grid, 256>>>(k, w_k, b_k, kp, ROWS, HID, HID);
    sgemm_bias_kernel<<<gemm_grid, 256>>>(v, w_v, b_v, vp, ROWS, HID, HID);

    const int attn_smem = 4 * 64 * 64 * (int)sizeof(float); // 65536 B
    cudaFuncSetAttribute(attn_kernel, cudaFuncAttributeMaxDynamicSharedMemorySize, attn_smem);
    attn_kernel<<<dim3(SEQ / ATQ, NHEAD, BATCH), 128, attn_smem>>>(qp, kp, vp, mask, ctx);

    sgemm_bias_kernel<<<gemm_grid, 256>>>(ctx, w_o, b_o, out, ROWS, HID, HID);
}

// round 12
// speedup vs baseline: 1.1276x; 1.1276x over previous
#include <cuda_runtime.h>
#include <cuda_bf16.h>
#include <math.h>
#include <stdint.h>

// Problem dims (fixed by the dataset)
#define BATCH   2
#define SEQ     2048
#define HID     1024
#define NHEAD   16
#define DH      64          // head dim
#define ROWS    (BATCH*SEQ) // 4096

// ---------------- scratch (no allocs allowed) ----------------
__device__ float g_qp[ROWS * HID];
__device__ float g_kp[ROWS * HID];
__device__ float g_vp[ROWS * HID];
__device__ float g_ctx[ROWS * HID];

// ---------------- f32x2 packed helpers (sm_103a) ----------------
typedef unsigned long long u64f2;

__device__ __forceinline__ void fma2(u64f2 &d, u64f2 a, u64f2 b) {
    asm("fma.rn.f32x2 %0, %1, %2, %0;" : "+l"(d) : "l"(a), "l"(b));
}
__device__ __forceinline__ u64f2 pack2(float lo, float hi) {
    u64f2 r; asm("mov.b64 %0, {%1, %2};" : "=l"(r) : "f"(lo), "f"(hi)); return r;
}
__device__ __forceinline__ float2 unpack2(u64f2 v) {
    float2 r; asm("mov.b64 {%0, %1}, %2;" : "=f"(r.x), "=f"(r.y) : "l"(v)); return r;
}
__device__ __forceinline__ void mul2(u64f2 &d, u64f2 a) {
    asm("mul.rn.f32x2 %0, %0, %1;" : "+l"(d) : "l"(a));
}

// ---------------- warp-MMA helpers (non-accelerated PTX: ok on sm_103) ----------------
__device__ __forceinline__ uint32_t smem_u32(const void* p) {
    uint32_t a;
    asm("{ .reg .u64 t; cvta.to.shared.u64 t, %1; cvt.u32.u64 %0, t; }" : "=r"(a) : "l"(p));
    return a;
}
__device__ __forceinline__ void ldm_x4(uint32_t r[4], uint32_t addr) {
    asm volatile("ldmatrix.sync.aligned.m8n8.x4.shared.b16 {%0,%1,%2,%3}, [%4];"
        : "=r"(r[0]), "=r"(r[1]), "=r"(r[2]), "=r"(r[3]) : "r"(addr));
}
__device__ __forceinline__ void mma_bf16(float d[4], const uint32_t a[4],
                                         uint32_t b0, uint32_t b1) {
    asm volatile("mma.sync.aligned.m16n8k16.row.col.f32.bf16.bf16.f32 "
        "{%0,%1,%2,%3}, {%4,%5,%6,%7}, {%8,%9}, {%0,%1,%2,%3};"
        : "+f"(d[0]), "+f"(d[1]), "+f"(d[2]), "+f"(d[3])
        : "r"(a[0]), "r"(a[1]), "r"(a[2]), "r"(a[3]), "r"(b0), "r"(b1));
}

// ---------------- tensor-core GEMM via mma.sync (bf16 2-term split) ----------------
// C[M,N] = A[M,K] @ B[K,N] + bias.  CTA tile 128x128, BK=64, 256 threads (8 warps 4x2),
// warp tile 32x64.  smem rows padded to 72 bf16 (144B) -> ldmatrix conflict-free.
#define GBK   64
#define GSTRB 144                 // bytes per smem row (72 bf16)
#define SM_AHI 0
#define SM_ALO (128*GSTRB)        // 18432
#define SM_BHI (2*128*GSTRB)      // 36864
#define SM_BLO (3*128*GSTRB)      // 55296
#define SM_TOT (4*128*GSTRB)      // 73728

__global__ __launch_bounds__(256) void gemm_mma_kernel(
    const float* __restrict__ A, const float* __restrict__ B,
    const float* __restrict__ bias, float* __restrict__ C,
    int M, int N, int K)
{
    extern __shared__ __align__(16) char smc[];
    const uint32_t sb = smem_u32(smc);
    const int tid = threadIdx.x;
    const int wid = tid >> 5, lane = tid & 31;
    const int m0w = (wid & 3) * 32;       // warp m offset in tile
    const int n0w = (wid >> 2) * 64;      // warp n offset in tile
    const int row0 = blockIdx.y * 128;
    const int col0 = blockIdx.x * 128;

    // ldmatrix lane->row/col mapping (same for A and B^T fragments)
    const int lrow  = (lane & 7) + ((lane >> 3) & 1) * 8;
    const int lcolb = (lane >> 4) * 16;   // byte offset of k-half (8 bf16)

    float acc[2][8][4];
#pragma unroll
    for (int mt = 0; mt < 2; mt++)
#pragma unroll
        for (int nt = 0; nt < 8; nt++)
#pragma unroll
            for (int e = 0; e < 4; e++) acc[mt][nt][e] = 0.f;

    const int nchunk = K / GBK;
    for (int kc = 0; kc < nchunk; kc++) {
        __syncthreads();   // previous iteration's ldmatrix reads complete

        // ---- fill A tile: [128 m][64 k] fp32 -> bf16 hi/lo ----
        {
            const float* Ag = A + (size_t)row0 * K + kc * GBK;
#pragma unroll
            for (int t = 0; t < 8; t++) {
                const int f = t * 256 + tid;
                const int r = f >> 4, c4 = f & 15;
                float4 av = *reinterpret_cast<const float4*>(Ag + (size_t)r * K + c4 * 4);
                __nv_bfloat16 h0 = __float2bfloat16_rn(av.x);
                __nv_bfloat16 h1 = __float2bfloat16_rn(av.y);
                __nv_bfloat16 h2 = __float2bfloat16_rn(av.z);
                __nv_bfloat16 h3 = __float2bfloat16_rn(av.w);
                __nv_bfloat16 l0 = __float2bfloat16_rn(av.x - __bfloat162float(h0));
                __nv_bfloat16 l1 = __float2bfloat16_rn(av.y - __bfloat162float(h1));
                __nv_bfloat16 l2 = __float2bfloat16_rn(av.z - __bfloat162float(h2));
                __nv_bfloat16 l3 = __float2bfloat16_rn(av.w - __bfloat162float(h3));
                const int byo = r * GSTRB + c4 * 8;
                __nv_bfloat162 hp0; hp0.x = h0; hp0.y = h1;
                __nv_bfloat162 hp1; hp1.x = h2; hp1.y = h3;
                __nv_bfloat162 lp0; lp0.x = l0; lp0.y = l1;
                __nv_bfloat162 lp1; lp1.x = l2; lp1.y = l3;
                *reinterpret_cast<__nv_bfloat162*>(smc + SM_AHI + byo)     = hp0;
                *reinterpret_cast<__nv_bfloat162*>(smc + SM_AHI + byo + 4) = hp1;
                *reinterpret_cast<__nv_bfloat162*>(smc + SM_ALO + byo)     = lp0;
                *reinterpret_cast<__nv_bfloat162*>(smc + SM_ALO + byo + 4) = lp1;
            }
        }
        // ---- fill B tile: [64 k][128 n] fp32 -> transposed [n][k] bf16 hi/lo ----
        {
            const float* Bg = B + (size_t)(kc * GBK) * N + col0;
#pragma unroll
            for (int t = 0; t < 8; t++) {
                const int f = t * 256 + tid;
                const int k = f >> 5, n4 = (f & 31) * 4;
                float4 bv = *reinterpret_cast<const float4*>(Bg + (size_t)k * N + n4);
                float vv[4] = {bv.x, bv.y, bv.z, bv.w};
#pragma unroll
                for (int u = 0; u < 4; u++) {
                    __nv_bfloat16 h = __float2bfloat16_rn(vv[u]);
                    __nv_bfloat16 l = __float2bfloat16_rn(vv[u] - __bfloat162float(h));
                    const int byo = (n4 + u) * GSTRB + k * 2;
                    *reinterpret_cast<__nv_bfloat16*>(smc + SM_BHI + byo) = h;
                    *reinterpret_cast<__nv_bfloat16*>(smc + SM_BLO + byo) = l;
                }
            }
        }
        __syncthreads();

        // ---- compute: 4 k16 steps ----
#pragma unroll
        for (int ks = 0; ks < 4; ks++) {
            const int kb = ks * 32;   // byte offset of this k16 block
            uint32_t ah[2][4], al[2][4], bf[4][4];
            uint32_t rbs[4];
#pragma unroll
            for (int mt = 0; mt < 2; mt++) {
                const uint32_t ra = sb + SM_AHI + (m0w + mt * 16 + lrow) * GSTRB + kb + lcolb;
                ldm_x4(ah[mt], ra);
                ldm_x4(al[mt], ra + (SM_ALO - SM_AHI));
            }
#pragma unroll
            for (int ng = 0; ng < 4; ng++) {
                rbs[ng] = sb + SM_BHI + (n0w + ng * 16 + lrow) * GSTRB + kb + lcolb;
                ldm_x4(bf[ng], rbs[ng]);
            }
            // hi*hi + lo*hi
#pragma unroll
            for (int mt = 0; mt < 2; mt++)
#pragma unroll
                for (int ng = 0; ng < 4; ng++) {
                    mma_bf16(acc[mt][2 * ng],     ah[mt], bf[ng][0], bf[ng][2]);
                    mma_bf16(acc[mt][2 * ng + 1], ah[mt], bf[ng][1], bf[ng][3]);
                    mma_bf16(acc[mt][2 * ng],     al[mt], bf[ng][0], bf[ng][2]);
                    mma_bf16(acc[mt][2 * ng + 1], al[mt], bf[ng][1], bf[ng][3]);
                }
            // reload B as lo: hi*lo
#pragma unroll
            for (int ng = 0; ng < 4; ng++)
                ldm_x4(bf[ng], rbs[ng] + (SM_BLO - SM_BHI));
#pragma unroll
            for (int mt = 0; mt < 2; mt++)
#pragma unroll
                for (int ng = 0; ng < 4; ng++) {
                    mma_bf16(acc[mt][2 * ng],     ah[mt], bf[ng][0], bf[ng][2]);
                    mma_bf16(acc[mt][2 * ng + 1], ah[mt], bf[ng][1], bf[ng][3]);
                }
        }
    }

    // ---- epilogue: D fragment (m16n8): d0,d1 @ (row, 2c), d2,d3 @ (row+8, 2c) ----
    const int mrow = lane >> 2;
    const int mcol = (lane & 3) * 2;
#pragma unroll
    for (int mt = 0; mt < 2; mt++) {
#pragma unroll
        for (int nt = 0; nt < 8; nt++) {
            const int gc = col0 + n0w + nt * 8 + mcol;
            const float b0 = bias[gc], b1 = bias[gc + 1];
            const int gr = row0 + m0w + mt * 16 + mrow;
            float* cp0 = C + (size_t)gr * N + gc;
            float* cp1 = cp0 + (size_t)8 * N;
            *reinterpret_cast<float2*>(cp0) = make_float2(acc[mt][nt][0] + b0,
                                                          acc[mt][nt][1] + b1);
            *reinterpret_cast<float2*>(cp1) = make_float2(acc[mt][nt][2] + b0,
                                                          acc[mt][nt][3] + b1);
        }
    }
}

// ---------------- flash attention (fp32 + f32x2, pack-free) — unchanged R7 ----------------
#define ATQ 64
#define ATK 64

__global__ __launch_bounds__(128) void attn_kernel(
    const float* __restrict__ qp, const float* __restrict__ kp,
    const float* __restrict__ vp, const int* __restrict__ mask,
    float* __restrict__ ctx)
{
    extern __shared__ float sm[];
    float* Qs = sm;               // [64][64] plain
    float* Ks = sm + 4096;        // [64][64] swizzled (row=k, col=d)
    float* Vs = sm + 8192;        // [64][64] TRANSPOSED swizzled (row=d, col=k)
    float* Ps = sm + 12288;       // [64][64] plain (row=q, col=k)

    const int tid = threadIdx.x;
    const int qt = blockIdx.x, h = blockIdx.y, b = blockIdx.z;
    const int q0 = qt * ATQ;
    const int tr = tid >> 4;
    const int tc = tid & 15;

    const float* qbase = qp + ((size_t)(b * SEQ + q0) * HID) + h * DH;
    const float* kbase = kp + ((size_t)b * SEQ) * HID + h * DH;
    const float* vbase = vp + ((size_t)b * SEQ) * HID + h * DH;
    const int*   mbase = mask + (size_t)(b * SEQ + q0) * SEQ;

#pragma unroll
    for (int t = 0; t < 8; t++) {
        const int f = t * 128 + tid;
        const int r = f >> 4, c4 = f & 15;
        *reinterpret_cast<float4*>(&Qs[r * 64 + c4 * 4]) =
            *reinterpret_cast<const float4*>(&qbase[(size_t)r * HID + c4 * 4]);
    }

    float m[8], l[8];
    u64f2 acc2[8][4];
#pragma unroll
    for (int i = 0; i < 8; i++) {
        m[i] = -1e30f; l[i] = 0.f;
#pragma unroll
        for (int j = 0; j < 4; j++) acc2[i][j] = 0ull;
    }

    const float scale = 0.125f;

    for (int kt = 0; kt < SEQ; kt += ATK) {
        __syncthreads();
#pragma unroll
        for (int t = 0; t < 8; t++) {
            const int f = t * 128 + tid;
            const int r = f >> 4, c4 = f & 15;
            float4 kv = *reinterpret_cast<const float4*>(&kbase[(size_t)(kt + r) * HID + c4 * 4]);
            float4 vv = *reinterpret_cast<const float4*>(&vbase[(size_t)(kt + r) * HID + c4 * 4]);
            const int kslot = c4 ^ (r >> 2);
            *reinterpret_cast<float4*>(&Ks[r * 64 + kslot * 4]) = kv;
            const int voff = (((r >> 2) ^ c4) << 2) | (r & 3);
            Vs[(c4 * 4 + 0) * 64 + voff] = vv.x;
            Vs[(c4 * 4 + 1) * 64 + voff] = vv.y;
            Vs[(c4 * 4 + 2) * 64 + voff] = vv.z;
            Vs[(c4 * 4 + 3) * 64 + voff] = vv.w;
        }
        __syncthreads();

        u64f2 s2[8][4];
#pragma unroll
        for (int i = 0; i < 8; i++)
#pragma unroll
            for (int j = 0; j < 4; j++) s2[i][j] = 0ull;

        {
            const float* qrow = Qs + (tr * 8) * 64;
            const float* krow = Ks + (tc * 4) * 64;
#pragma unroll 4
            for (int kk = 0; kk < ATK; kk += 2) {
                const int so = (((kk >> 2) ^ tc) << 2) | (kk & 3);
                u64f2 b2[4];
#pragma unroll
                for (int j = 0; j < 4; j++)
                    b2[j] = *reinterpret_cast<const u64f2*>(krow + j * 64 + so);
#pragma unroll
                for (int i = 0; i < 8; i++) {
                    const u64f2 a2 = *reinterpret_cast<const u64f2*>(qrow + i * 64 + kk);
#pragma unroll
                    for (int j = 0; j < 4; j++)
                        fma2(s2[i][j], a2, b2[j]);
                }
            }
        }

#pragma unroll
        for (int i = 0; i < 8; i++) {
            float s[4];
#pragma unroll
            for (int j = 0; j < 4; j++) {
                float2 v = unpack2(s2[i][j]);
                s[j] = v.x + v.y;
            }
            const int4 mk = *reinterpret_cast<const int4*>(
                mbase + (size_t)(tr * 8 + i) * SEQ + kt + tc * 4);
            s[0] = mk.x ? s[0] * scale : -10000.f;
            s[1] = mk.y ? s[1] * scale : -10000.f;
            s[2] = mk.z ? s[2] * scale : -10000.f;
            s[3] = mk.w ? s[3] * scale : -10000.f;

            float mt = fmaxf(fmaxf(s[0], s[1]), fmaxf(s[2], s[3]));
#pragma unroll
            for (int off = 8; off; off >>= 1)
                mt = fmaxf(mt, __shfl_xor_sync(0xffffffffu, mt, off));
            const float mn = fmaxf(m[i], mt);
            const float alpha = __expf(m[i] - mn);
            m[i] = mn;

            float lt = 0.f;
#pragma unroll
            for (int j = 0; j < 4; j++) {
                s[j] = __expf(s[j] - mn);
                lt += s[j];
            }
#pragma unroll
            for (int off = 8; off; off >>= 1)
                lt += __shfl_xor_sync(0xffffffffu, lt, off);
            l[i] = l[i] * alpha + lt;

            const u64f2 al2 = pack2(alpha, alpha);
#pragma unroll
            for (int j = 0; j < 4; j++) mul2(acc2[i][j], al2);

            *reinterpret_cast<float4*>(&Ps[(tr * 8 + i) * 64 + tc * 4]) =
                make_float4(s[0], s[1], s[2], s[3]);
        }
        __syncthreads();

        {
            const float* prow = Ps + (tr * 8) * 64;
            const float* vrow = Vs + (tc * 4) * 64;
#pragma unroll 4
            for (int kk = 0; kk < ATK; kk += 2) {
                const int so = (((kk >> 2) ^ tc) << 2) | (kk & 3);
                u64f2 v2[4];
#pragma unroll
                for (int j = 0; j < 4; j++)
                    v2[j] = *reinterpret_cast<const u64f2*>(vrow + j * 64 + so);
#pragma unroll
                for (int i = 0; i < 8; i++) {
                    const u64f2 a2 = *reinterpret_cast<const u64f2*>(prow + i * 64 + kk);
#pragma unroll
                    for (int j = 0; j < 4; j++)
                        fma2(acc2[i][j], a2, v2[j]);
                }
            }
        }
    }

#pragma unroll
    for (int i = 0; i < 8; i++) {
        const float inv = 1.f / l[i];
        const int q = q0 + tr * 8 + i;
        float* o = ctx + ((size_t)(b * SEQ + q) * HID) + h * DH + tc * 4;
        float r[4];
#pragma unroll
        for (int j = 0; j < 4; j++) {
            float2 v = unpack2(acc2[i][j]);
            r[j] = (v.x + v.y) * inv;
        }
        *reinterpret_cast<float4*>(o) = make_float4(r[0], r[1], r[2], r[3]);
    }
}

// ---------------- launch ----------------
extern "C" void kernel_launch(void* const* d_in, const int* in_sizes, int n_in,
                              void* d_out, int out_size)
{
    const float* q    = (const float*)d_in[0];
    const float* k    = (const float*)d_in[1];
    const float* v    = (const float*)d_in[2];
    const int*   mask = (const int*)  d_in[3];
    const float* w_q  = (const float*)d_in[4];
    const float* b_q  = (const float*)d_in[5];
    const float* w_k  = (const float*)d_in[6];
    const float* b_k  = (const float*)d_in[7];
    const float* w_v  = (const float*)d_in[8];
    const float* b_v  = (const float*)d_in[9];
    const float* w_o  = (const float*)d_in[10];
    const float* b_o  = (const float*)d_in[11];
    float* out = (float*)d_out;

    float *qp, *kp, *vp, *ctx;
    cudaGetSymbolAddress((void**)&qp,  g_qp);
    cudaGetSymbolAddress((void**)&kp,  g_kp);
    cudaGetSymbolAddress((void**)&vp,  g_vp);
    cudaGetSymbolAddress((void**)&ctx, g_ctx);

    cudaFuncSetAttribute(gemm_mma_kernel, cudaFuncAttributeMaxDynamicSharedMemorySize, SM_TOT);

    const dim3 gemm_grid(HID / 128, ROWS / 128);  // (8, 32)
    gemm_mma_kernel<<<gemm_grid, 256, SM_TOT>>>(q, w_q, b_q, qp, ROWS, HID, HID);
    gemm_mma_kernel<<<gemm_grid, 256, SM_TOT>>>(k, w_k, b_k, kp, ROWS, HID, HID);
    gemm_mma_kernel<<<gemm_grid, 256, SM_TOT>>>(v, w_v, b_v, vp, ROWS, HID, HID);

    const int attn_smem = 4 * 64 * 64 * (int)sizeof(float); // 65536 B
    cudaFuncSetAttribute(attn_kernel, cudaFuncAttributeMaxDynamicSharedMemorySize, attn_smem);
    attn_kernel<<<dim3(SEQ / ATQ, NHEAD, BATCH), 128, attn_smem>>>(qp, kp, vp, mask, ctx);

    gemm_mma_kernel<<<gemm_grid, 256, SM_TOT>>>(ctx, w_o, b_o, out, ROWS, HID, HID);
}